// round 11
// baseline (speedup 1.0000x reference)
#include <cuda_runtime.h>
#include <cuda_bf16.h>
#include <cstdint>

// Problem constants
#define BB   128
#define SS   37
#define TT   2048
#define DD   256
#define STT  8
#define CC   2
#define MER  264
#define NF   74

#define NT    512
#define NBLK  296            // 2 * 148; 4736 units / 296 = 16
#define UPB   16             // (b,s) units per block
#define NPOS  512            // float4 positions per row

// tail merge GEMV split
#define G2   6
#define Q2   66
#define KI2  (MER / G2)   // 44

// ---------------- device scratch ----------------
__device__ float    gA[BB * NF];             // owner-written each launch
__device__ unsigned gNZbits[NBLK * 2 * 64];  // [blk][seg][64 words] write-once
__device__ int      gCnt[BB];                // unit counters (reset after tail)

__device__ __forceinline__ float wredf(float v) {
    #pragma unroll
    for (int o = 16; o; o >>= 1) v += __shfl_xor_sync(0xffffffffu, v, o);
    return v;
}
__device__ __forceinline__ float wred3(float v) {
    v += __shfl_xor_sync(0xffffffffu, v, 16);
    v += __shfl_xor_sync(0xffffffffu, v, 8);
    v += __shfl_xor_sync(0xffffffffu, v, 4);
    return v;
}
__device__ __forceinline__ void pf_l2(const void* p) {
    asm volatile("prefetch.global.L2 [%0];" :: "l"(p));
}

__global__ __launch_bounds__(NT, 2)   // <=64 regs -> all 296 blocks co-resident
void fused_kernel(const float* __restrict__ x,
                  const int*   __restrict__ smask,
                  const float* __restrict__ tim,
                  const float* __restrict__ stat,
                  const float* __restrict__ Ws,   // [NF, DD]
                  const float* __restrict__ bs,
                  const float* __restrict__ Wt,   // [1, DD]
                  const float* __restrict__ bt,
                  const float* __restrict__ Wst,  // [STT, STT]
                  const float* __restrict__ bst,
                  const float* __restrict__ Wm,   // [MER, MER]
                  const float* __restrict__ bm,
                  const float* __restrict__ Wc,   // [MER, CC]
                  const float* __restrict__ bc,
                  float* __restrict__ out) {
    const int j    = blockIdx.x;
    const int tid  = threadIdx.x;
    const int w    = tid >> 5;
    const int lane = tid & 31;

    __shared__ float  sU[UPB * 128];    // [unit][q(2)][64 partials]  8 KB
    __shared__ float  sAll[80];
    __shared__ float  comb[MER];
    __shared__ float4 sH4[G2 * Q2];
    __shared__ float  sMs[16], sMt[16];
    __shared__ float  outc[CC];
    __shared__ int    doTail[2];

    // ---- L2 prefetch of weights (spread across grid), fire-and-forget ----
    {
        unsigned r = (unsigned)j * NT + tid;
        const unsigned LWs = (NF * DD * 4) / 128;     // 592
        const unsigned LWm = (MER * MER * 4) / 128;   // 2178
        if (r < LWs) { pf_l2((const char*)Ws + r * 128u); }
        else { r -= LWs;
        if (r < LWm) { pf_l2((const char*)Wm + r * 128u); }
        else { r -= LWm;
        if (r < 17) { pf_l2((const char*)Wc + r * 128u); }
        else { r -= 17;
        if (r < 8) { pf_l2((const char*)bs + r * 128u); }
        else { r -= 8;
        if (r < 8) { pf_l2((const char*)bt + r * 128u); }
        else { r -= 8;
        if (r < 8) { pf_l2((const char*)Wt + r * 128u); }
        else { r -= 8;
        if (r < 9) { pf_l2((const char*)bm + r * 128u); }
        else { r -= 9;
        if (r < 32) { pf_l2((const char*)stat + r * 128u); }
        else { r -= 32;
        if (r < 2) { pf_l2((const char*)Wst + r * 128u); }
        else { r -= 2;
        if (r < 1) { pf_l2((const char*)bst); }
        else { r -= 1;
        if (r < 1) { pf_l2((const char*)bc); }
        }}}}}}}}}}
    }

    // ================= Phase 1: stream 16 contiguous (b,s) units ============
    const int u0      = j * UPB;
    const int bA      = u0 / SS;
    const int uswitch = (bA + 1) * SS;       // first unit of next batch
    const int nA      = (uswitch < u0 + UPB) ? (uswitch - u0) : UPB;
    const int nB      = UPB - nA;
    const int bBb     = bA + 1;

    const float4* __restrict__ x4 = (const float4*)x;
    const int4*   __restrict__ m4 = (const int4*)smask;

    float4 nzA = make_float4(0.f, 0.f, 0.f, 0.f);
    float4 nzB = make_float4(0.f, 0.f, 0.f, 0.f);

    #pragma unroll 8
    for (int k = 0; k < UPB; ++k) {
        const int u = u0 + k;
        const float4 xv = __ldcs(x4 + (size_t)u * NPOS + tid);
        const int4   mv = __ldcs(m4 + (size_t)u * NPOS + tid);

        float ax = (xv.x + xv.y) + (xv.z + xv.w);
        float am = (float)((mv.x + mv.y) + (mv.z + mv.w));

        float4 c;
        c.x = fabsf(xv.x) + (float)mv.x;
        c.y = fabsf(xv.y) + (float)mv.y;
        c.z = fabsf(xv.z) + (float)mv.z;
        c.w = fabsf(xv.w) + (float)mv.w;
        if (u < uswitch) {
            nzA.x += c.x; nzA.y += c.y; nzA.z += c.z; nzA.w += c.w;
        } else {
            nzB.x += c.x; nzB.y += c.y; nzB.z += c.z; nzB.w += c.w;
        }

        ax = wred3(ax);
        am = wred3(am);
        if (lane < 4) {
            sU[k * 128 +      w * 4 + lane] = ax;
            sU[k * 128 + 64 + w * 4 + lane] = am;
        }
    }

    // pack nz -> bitmask words: word[w*4+k] bit lane covers t = 128w + 4*lane + k
    {
        unsigned a0 = __ballot_sync(0xffffffffu, nzA.x > 0.f);
        unsigned a1 = __ballot_sync(0xffffffffu, nzA.y > 0.f);
        unsigned a2 = __ballot_sync(0xffffffffu, nzA.z > 0.f);
        unsigned a3 = __ballot_sync(0xffffffffu, nzA.w > 0.f);
        unsigned b0 = __ballot_sync(0xffffffffu, nzB.x > 0.f);
        unsigned b1 = __ballot_sync(0xffffffffu, nzB.y > 0.f);
        unsigned b2 = __ballot_sync(0xffffffffu, nzB.z > 0.f);
        unsigned b3 = __ballot_sync(0xffffffffu, nzB.w > 0.f);
        if (lane < 4) {
            const unsigned va = (lane == 0) ? a0 : (lane == 1) ? a1 : (lane == 2) ? a2 : a3;
            const unsigned vb = (lane == 0) ? b0 : (lane == 1) ? b1 : (lane == 2) ? b2 : b3;
            __stcg(&gNZbits[(j * 2 + 0) * 64 + w * 4 + lane], va);
            __stcg(&gNZbits[(j * 2 + 1) * 64 + w * 4 + lane], vb);
        }
    }
    __syncthreads();

    // combine unit partials -> gA (owner-written, fixed order)
    if (tid < 32) {
        const int k = tid >> 1, q = tid & 1;
        const float4* p = (const float4*)&sU[k * 128 + q * 64];
        float acc = 0.f;
        #pragma unroll
        for (int u2 = 0; u2 < 16; ++u2) {
            const float4 v = p[u2];
            acc += (v.x + v.y) + (v.z + v.w);
        }
        const int u = u0 + k, bb = u / SS, s = u - bb * SS;
        __stcg(&gA[bb * NF + q * SS + s], acc);
    }

    // ---- completion counters: last contributor runs the batch tail ----
    __threadfence();
    __syncthreads();
    if (tid == 0) {
        doTail[0] = (atomicAdd(&gCnt[bA], nA) + nA == SS) ? 1 : 0;
        doTail[1] = 0;
        if (nB > 0)
            doTail[1] = (atomicAdd(&gCnt[bBb], nB) + nB == SS) ? 1 : 0;
        __threadfence();   // acquire: later reads see all contributors' writes
    }
    __syncthreads();

    #pragma unroll 1
    for (int seg = 0; seg < 2; ++seg) {
        if (!doTail[seg]) continue;
        const int b = bA + seg;

        // -------- reconstruct nz bits, msum/tmsum --------
        {
            const int j0 = (SS * b) / UPB;
            const int j1 = (SS * b + SS - 1) / UPB;
            uint4 acc = make_uint4(0u, 0u, 0u, 0u);
            for (int jj = j0; jj <= j1; ++jj) {
                const int sg = b - (UPB * jj) / SS;   // 0 or 1
                const unsigned* wp = &gNZbits[(jj * 2 + sg) * 64 + (tid >> 5) * 4];
                const uint4 v = make_uint4(__ldcg(wp + 0), __ldcg(wp + 1),
                                           __ldcg(wp + 2), __ldcg(wp + 3));
                acc.x |= v.x; acc.y |= v.y; acc.z |= v.z; acc.w |= v.w;
            }
            const unsigned bit = 1u << (tid & 31);
            const float4 tv = ((const float4*)(tim + (size_t)b * TT))[tid];
            float ms = 0.f, tm = 0.f;
            if (acc.x & bit) { ms += 1.f; tm += tv.x; }
            if (acc.y & bit) { ms += 1.f; tm += tv.y; }
            if (acc.z & bit) { ms += 1.f; tm += tv.z; }
            if (acc.w & bit) { ms += 1.f; tm += tv.w; }
            ms = wredf(ms);
            tm = wredf(tm);
            if (lane == 0) { sMs[w] = ms; sMt[w] = tm; }
        }
        if (tid < CC) outc[tid] = 0.f;
        __syncthreads();

        if (tid < NF) sAll[tid] = __ldcg(&gA[b * NF + tid]);
        if (tid == NF || tid == NF + 1) {
            const float* src = (tid == NF) ? sMs : sMt;
            float acc = 0.f;
            #pragma unroll
            for (int w2 = 0; w2 < 16; ++w2) acc += src[w2];
            sAll[tid] = acc;
        }
        __syncthreads();

        const float msum  = sAll[74];
        const float tmsum = sAll[75];
        const float inv   = 1.f / fmaxf(msum, 1e-9f);

        // ---- A: comb[MER] ----
        if (tid < DD) {
            float acc = 0.f;
            #pragma unroll 8
            for (int f = 0; f < NF; ++f) acc += sAll[f] * Ws[f * DD + tid];
            acc += msum * (bs[tid] + bt[tid]) + tmsum * Wt[tid];
            comb[tid] = acc * inv;
        } else if (tid < MER) {
            const int jj = tid - DD;
            float acc = bst[jj];
            #pragma unroll
            for (int q = 0; q < STT; ++q) acc += stat[b * STT + q] * Wst[q * STT + jj];
            comb[tid] = acc;
        }
        __syncthreads();

        // ---- B: merge GEMV split-i, float4 columns ----
        if (tid < G2 * Q2) {
            const int q  = tid % Q2;
            const int gg = tid / Q2;
            const float4* __restrict__ Wm4 = (const float4*)Wm;
            float4 acc = make_float4(0.f, 0.f, 0.f, 0.f);
            #pragma unroll
            for (int kk = 0; kk < KI2; ++kk) {
                const int ii = gg * KI2 + kk;
                const float  c  = comb[ii];
                const float4 wv = Wm4[ii * Q2 + q];
                acc.x += c * wv.x;
                acc.y += c * wv.y;
                acc.z += c * wv.z;
                acc.w += c * wv.w;
            }
            sH4[gg * Q2 + q] = acc;
        }
        __syncthreads();

        // ---- C: reduce, ReLU, classifier ----
        float p0 = 0.f, p1 = 0.f;
        if (tid < MER) {
            const float* sH = (const float*)sH4;
            float t = bm[tid];
            #pragma unroll
            for (int gg = 0; gg < G2; ++gg) t += sH[gg * MER + tid];
            const float h = fmaxf(t, 0.f);
            p0 = h * Wc[tid * CC + 0];
            p1 = h * Wc[tid * CC + 1];
        }
        p0 = wredf(p0);
        p1 = wredf(p1);
        if (lane == 0) {
            atomicAdd(&outc[0], p0);
            atomicAdd(&outc[1], p1);
        }
        __syncthreads();

        if (tid < CC) out[b * CC + tid] = outc[tid] + bc[tid];
        if (tid == 0) gCnt[b] = 0;     // reset for next launch (no racers left)
        __syncthreads();
    }
}

// ---------------- launch ----------------
extern "C" void kernel_launch(void* const* d_in, const int* in_sizes, int n_in,
                              void* d_out, int out_size) {
    const float* x     = (const float*)d_in[0];
    const float* stat  = (const float*)d_in[1];
    const float* tim   = (const float*)d_in[2];
    const int*   smask = (const int*)  d_in[3];
    const float* Ws    = (const float*)d_in[4];
    const float* bs    = (const float*)d_in[5];
    const float* Wt    = (const float*)d_in[6];
    const float* bt    = (const float*)d_in[7];
    const float* Wst   = (const float*)d_in[8];
    const float* bst   = (const float*)d_in[9];
    const float* Wm    = (const float*)d_in[10];
    const float* bm    = (const float*)d_in[11];
    const float* Wc    = (const float*)d_in[12];
    const float* bc    = (const float*)d_in[13];
    float* out = (float*)d_out;

    fused_kernel<<<NBLK, NT>>>(x, smask, tim, stat, Ws, bs, Wt, bt,
                               Wst, bst, Wm, bm, Wc, bc, out);
}

// round 12
// speedup vs baseline: 1.1664x; 1.1664x over previous
#include <cuda_runtime.h>
#include <cuda_bf16.h>
#include <cstdint>

// Problem constants
#define BB   128
#define SS   37
#define TT   2048
#define DD   256
#define STT  8
#define CC   2
#define MER  264
#define NF   74

#define NT    512
#define DST   8                       // cp.async ring depth (stages)
#define SLOTB 16384                   // bytes per stage: 512*16 (x) + 512*16 (mask)
#define SMEM_DYN (DST * SLOTB)        // 128 KB

// per-warp partial layout: 76 quantities x 4 partials
#define PW   312

// tail merge GEMV split
#define G2   6
#define Q2   66
#define KI2  (MER / G2)   // 44

__device__ __forceinline__ float wredf(float v) {
    #pragma unroll
    for (int o = 16; o; o >>= 1) v += __shfl_xor_sync(0xffffffffu, v, o);
    return v;
}
__device__ __forceinline__ float wred3(float v) {
    v += __shfl_xor_sync(0xffffffffu, v, 16);
    v += __shfl_xor_sync(0xffffffffu, v, 8);
    v += __shfl_xor_sync(0xffffffffu, v, 4);
    return v;
}
__device__ __forceinline__ void pf_l2(const void* p) {
    asm volatile("prefetch.global.L2 [%0];" :: "l"(p));
}
__device__ __forceinline__ void cp16(uint32_t dst, const void* src) {
    asm volatile("cp.async.cg.shared.global [%0], [%1], 16;" :: "r"(dst), "l"(src) : "memory");
}
__device__ __forceinline__ void cp_commit() {
    asm volatile("cp.async.commit_group;" ::: "memory");
}
template <int N>
__device__ __forceinline__ void cp_wait() {
    asm volatile("cp.async.wait_group %0;" :: "n"(N) : "memory");
}

__global__ __launch_bounds__(NT, 1)
void fused_kernel(const float* __restrict__ x,
                  const int*   __restrict__ smask,
                  const float* __restrict__ tim,
                  const float* __restrict__ stat,
                  const float* __restrict__ Ws,   // [NF, DD]
                  const float* __restrict__ bs,
                  const float* __restrict__ Wt,   // [1, DD]
                  const float* __restrict__ bt,
                  const float* __restrict__ Wst,  // [STT, STT]
                  const float* __restrict__ bst,
                  const float* __restrict__ Wm,   // [MER, MER]
                  const float* __restrict__ bm,
                  const float* __restrict__ Wc,   // [MER, CC]
                  const float* __restrict__ bc,
                  float* __restrict__ out) {
    extern __shared__ char dynbuf[];   // [DST][16KB]: x(8KB) | mask(8KB)

    const int b    = blockIdx.x;
    const int tid  = threadIdx.x;
    const int w    = tid >> 5;
    const int lane = tid & 31;

    __shared__ float sW[16 * PW];      // per-warp partials ~20 KB
    __shared__ float sAll[80];
    __shared__ float outc[CC];

    // tail scratch aliased into the ring (used only after streaming completes)
    float*  comb = (float*)dynbuf;                 // 264 floats
    float4* sH4  = (float4*)(dynbuf + 4096);       // G2*Q2 float4

    const uint32_t dyn0 = (uint32_t)__cvta_generic_to_shared(dynbuf);

    if (tid < CC) outc[tid] = 0.f;

    // ---- L2 prefetch of all weights (spread across grid), fire-and-forget ----
    {
        unsigned r = (unsigned)b * NT + tid;
        const unsigned LWs = (NF * DD * 4) / 128;     // 592
        const unsigned LWm = (MER * MER * 4) / 128;   // 2178
        if (r < LWs) { pf_l2((const char*)Ws + r * 128u); }
        else { r -= LWs;
        if (r < LWm) { pf_l2((const char*)Wm + r * 128u); }
        else { r -= LWm;
        if (r < 17) { pf_l2((const char*)Wc + r * 128u); }
        else { r -= 17;
        if (r < 8) { pf_l2((const char*)bs + r * 128u); }
        else { r -= 8;
        if (r < 8) { pf_l2((const char*)bt + r * 128u); }
        else { r -= 8;
        if (r < 8) { pf_l2((const char*)Wt + r * 128u); }
        else { r -= 8;
        if (r < 9) { pf_l2((const char*)bm + r * 128u); }
        else { r -= 9;
        if (r < 32) { pf_l2((const char*)stat + r * 128u); }
        else { r -= 32;
        if (r < 2) { pf_l2((const char*)Wst + r * 128u); }
        else { r -= 2;
        if (r < 1) { pf_l2((const char*)bst); }
        else { r -= 1;
        if (r < 1) { pf_l2((const char*)bc); }
        }}}}}}}}}}
    }

    // ================= Phase 1: cp.async ring over SS sensor rows ============
    const char* xrow = (const char*)x     + ((size_t)b * SS) * 8192 + (size_t)tid * 16;
    const char* mrow = (const char*)smask + ((size_t)b * SS) * 8192 + (size_t)tid * 16;
    const uint32_t myx = dyn0 + (uint32_t)tid * 16u;          // + slot*SLOTB
    const uint32_t mym = myx + 8192u;

    // prologue: issue stages 0..DST-2 (DST-1 groups)
    #pragma unroll
    for (int d = 0; d < DST - 1; ++d) {
        cp16(myx + (uint32_t)d * SLOTB, xrow + (size_t)d * 8192);
        cp16(mym + (uint32_t)d * SLOTB, mrow + (size_t)d * 8192);
        cp_commit();
    }

    const float4 tv = ((const float4*)(tim + (size_t)b * TT))[tid];

    float nz0 = 0.f, nz1 = 0.f, nz2 = 0.f, nz3 = 0.f;
    float* myrow = &sW[w * PW];

    int slot = 0;
    #pragma unroll 1
    for (int s = 0; s < SS; ++s) {
        const int nx = s + DST - 1;
        if (nx < SS) {
            const int ns = (slot + DST - 1) % DST;
            cp16(myx + (uint32_t)ns * SLOTB, xrow + (size_t)nx * 8192);
            cp16(mym + (uint32_t)ns * SLOTB, mrow + (size_t)nx * 8192);
            cp_commit();
            cp_wait<DST - 1>();
        } else {
            cp_wait<0>();
        }

        const float4 xv = *(const float4*)(dynbuf + (size_t)slot * SLOTB        + (size_t)tid * 16);
        const int4   mv = *(const int4*)  (dynbuf + (size_t)slot * SLOTB + 8192 + (size_t)tid * 16);

        float ax = (xv.x + xv.y) + (xv.z + xv.w);
        float am = (float)((mv.x + mv.y) + (mv.z + mv.w));

        nz0 += fabsf(xv.x) + (float)mv.x;
        nz1 += fabsf(xv.y) + (float)mv.y;
        nz2 += fabsf(xv.z) + (float)mv.z;
        nz3 += fabsf(xv.w) + (float)mv.w;

        ax = wred3(ax);
        am = wred3(am);
        if (lane < 4) {
            myrow[s * 4 + lane]        = ax;
            myrow[(SS + s) * 4 + lane] = am;
        }

        if (++slot == DST) slot = 0;
    }

    // mask count + masked time sum (each thread saw all sensors at its 4 t's)
    {
        float ms = 0.f, tm = 0.f;
        if (nz0 > 0.f) { ms += 1.f; tm += tv.x; }
        if (nz1 > 0.f) { ms += 1.f; tm += tv.y; }
        if (nz2 > 0.f) { ms += 1.f; tm += tv.z; }
        if (nz3 > 0.f) { ms += 1.f; tm += tv.w; }
        ms = wred3(ms);
        tm = wred3(tm);
        if (lane < 4) {
            myrow[74 * 4 + lane] = ms;
            myrow[75 * 4 + lane] = tm;
        }
    }
    __syncthreads();

    // final combine: 76 outputs, 16 warp-rows x 4 partials each
    if (tid < 76) {
        float acc = 0.f;
        #pragma unroll
        for (int w2 = 0; w2 < 16; ++w2) {
            const float4 p = *(const float4*)&sW[w2 * PW + tid * 4];
            acc += (p.x + p.y) + (p.z + p.w);
        }
        sAll[tid] = acc;
    }
    __syncthreads();   // also: ring reads done -> safe to alias comb/sH4

    // ================= Phase 2: per-batch tail (L2-warm) =================
    const float msum  = sAll[74];
    const float tmsum = sAll[75];
    const float inv   = 1.f / fmaxf(msum, 1e-9f);

    // ---- A: comb[MER] ----
    if (tid < DD) {
        float acc = 0.f;
        #pragma unroll 8
        for (int f = 0; f < NF; ++f) acc += sAll[f] * Ws[f * DD + tid];
        acc += msum * (bs[tid] + bt[tid]) + tmsum * Wt[tid];
        comb[tid] = acc * inv;
    } else if (tid < MER) {
        const int j = tid - DD;
        float acc = bst[j];
        #pragma unroll
        for (int q = 0; q < STT; ++q) acc += stat[b * STT + q] * Wst[q * STT + j];
        comb[tid] = acc;
    }
    __syncthreads();

    // ---- B: merge GEMV split-i, float4 columns ----
    if (tid < G2 * Q2) {
        const int q  = tid % Q2;
        const int gg = tid / Q2;
        const float4* __restrict__ Wm4 = (const float4*)Wm;
        float4 acc = make_float4(0.f, 0.f, 0.f, 0.f);
        #pragma unroll
        for (int kk = 0; kk < KI2; ++kk) {
            const int ii = gg * KI2 + kk;
            const float  c  = comb[ii];
            const float4 wv = Wm4[ii * Q2 + q];
            acc.x += c * wv.x;
            acc.y += c * wv.y;
            acc.z += c * wv.z;
            acc.w += c * wv.w;
        }
        sH4[gg * Q2 + q] = acc;
    }
    __syncthreads();

    // ---- C: reduce, ReLU, classifier ----
    float p0 = 0.f, p1 = 0.f;
    if (tid < MER) {
        const float* sH = (const float*)sH4;
        float t = bm[tid];
        #pragma unroll
        for (int gg = 0; gg < G2; ++gg) t += sH[gg * MER + tid];
        const float h = fmaxf(t, 0.f);
        p0 = h * Wc[tid * CC + 0];
        p1 = h * Wc[tid * CC + 1];
    }
    p0 = wredf(p0);
    p1 = wredf(p1);
    if (lane == 0) {
        atomicAdd(&outc[0], p0);
        atomicAdd(&outc[1], p1);
    }
    __syncthreads();

    if (tid < CC) out[b * CC + tid] = outc[tid] + bc[tid];
}

// ---------------- launch ----------------
extern "C" void kernel_launch(void* const* d_in, const int* in_sizes, int n_in,
                              void* d_out, int out_size) {
    const float* x     = (const float*)d_in[0];
    const float* stat  = (const float*)d_in[1];
    const float* tim   = (const float*)d_in[2];
    const int*   smask = (const int*)  d_in[3];
    const float* Ws    = (const float*)d_in[4];
    const float* bs    = (const float*)d_in[5];
    const float* Wt    = (const float*)d_in[6];
    const float* bt    = (const float*)d_in[7];
    const float* Wst   = (const float*)d_in[8];
    const float* bst   = (const float*)d_in[9];
    const float* Wm    = (const float*)d_in[10];
    const float* bm    = (const float*)d_in[11];
    const float* Wc    = (const float*)d_in[12];
    const float* bc    = (const float*)d_in[13];
    float* out = (float*)d_out;

    cudaFuncSetAttribute(fused_kernel,
                         cudaFuncAttributeMaxDynamicSharedMemorySize, SMEM_DYN);
    fused_kernel<<<BB, NT, SMEM_DYN>>>(x, smask, tim, stat, Ws, bs, Wt, bt,
                                       Wst, bst, Wm, bm, Wc, bc, out);
}

// round 16
// speedup vs baseline: 1.4877x; 1.2754x over previous
#include <cuda_runtime.h>
#include <cuda_bf16.h>
#include <cstdint>

// Problem constants
#define BB   128
#define SS   37
#define TT   2048
#define DD   256
#define STT  8
#define CC   2
#define MER  264
#define NF   74

#define NT   512
#define RF4  (TT / 4)   // 512 float4 per sensor row

// per-warp partial layout: 76 quantities x 4 partials, padded stride
#define PW   312

// tail merge GEMV split
#define G2   6
#define Q2   66
#define KI2  (MER / G2)   // 44

__device__ __forceinline__ float wredf(float v) {
    #pragma unroll
    for (int o = 16; o; o >>= 1) v += __shfl_xor_sync(0xffffffffu, v, o);
    return v;
}
// 3-level reduction: lanes 0-3 end with 4 disjoint partial sums
__device__ __forceinline__ float wred3(float v) {
    v += __shfl_xor_sync(0xffffffffu, v, 16);
    v += __shfl_xor_sync(0xffffffffu, v, 8);
    v += __shfl_xor_sync(0xffffffffu, v, 4);
    return v;
}
__device__ __forceinline__ void pf_l2(const void* p) {
    asm volatile("prefetch.global.L2 [%0];" :: "l"(p));
}

__global__ __launch_bounds__(NT, 1)
void fused_kernel(const float* __restrict__ x,
                  const int*   __restrict__ smask,
                  const float* __restrict__ tim,
                  const float* __restrict__ stat,
                  const float* __restrict__ Ws,   // [NF, DD]
                  const float* __restrict__ bs,
                  const float* __restrict__ Wt,   // [1, DD]
                  const float* __restrict__ bt,
                  const float* __restrict__ Wst,  // [STT, STT]
                  const float* __restrict__ bst,
                  const float* __restrict__ Wm,   // [MER, MER]
                  const float* __restrict__ bm,
                  const float* __restrict__ Wc,   // [MER, CC]
                  const float* __restrict__ bc,
                  float* __restrict__ out) {
    const int b    = blockIdx.x;
    const int tid  = threadIdx.x;
    const int w    = tid >> 5;
    const int lane = tid & 31;

    __shared__ float  sW[16 * PW];      // per-warp partials [warp][76*4]
    __shared__ float  sAll[80];
    __shared__ float  comb[MER];
    __shared__ float4 sH4[G2 * Q2];
    __shared__ float  outc[CC];

    if (tid < CC) outc[tid] = 0.f;

    // ---- L2 prefetch of all weights (spread across the grid), fire-and-forget ----
    {
        unsigned r = (unsigned)b * NT + tid;
        const unsigned LWs = (NF * DD * 4) / 128;     // 592
        const unsigned LWm = (MER * MER * 4) / 128;   // 2178
        if (r < LWs) { pf_l2((const char*)Ws + r * 128u); }
        else { r -= LWs;
        if (r < LWm) { pf_l2((const char*)Wm + r * 128u); }
        else { r -= LWm;
        if (r < 17) { pf_l2((const char*)Wc + r * 128u); }
        else { r -= 17;
        if (r < 8) { pf_l2((const char*)bs + r * 128u); }
        else { r -= 8;
        if (r < 8) { pf_l2((const char*)bt + r * 128u); }
        else { r -= 8;
        if (r < 8) { pf_l2((const char*)Wt + r * 128u); }
        else { r -= 8;
        if (r < 9) { pf_l2((const char*)bm + r * 128u); }
        else { r -= 9;
        if (r < 32) { pf_l2((const char*)stat + r * 128u); }
        else { r -= 32;
        if (r < 2) { pf_l2((const char*)Wst + r * 128u); }
        else { r -= 2;
        if (r < 1) { pf_l2((const char*)bst); }
        else { r -= 1;
        if (r < 1) { pf_l2((const char*)bc); }
        }}}}}}}}}}
    }

    // ================= Phase 1: streaming reduction over [SS, TT] =================
    const size_t baseb = (size_t)b * SS * TT;
    const float4* __restrict__ xp = (const float4*)(x     + baseb) + tid;
    const int4*   __restrict__ mp = (const int4*)  (smask + baseb) + tid;

    const float4 tv = *((const float4*)(tim + (size_t)b * TT) + tid);

    float nz0 = 0.f, nz1 = 0.f, nz2 = 0.f, nz3 = 0.f;
    float* myrow = &sW[w * PW];

    // chunks of 2 sensors, double-buffered: fits registers (no spills)
    float4 fx[2][2];
    int4   fm[2][2];

    #pragma unroll
    for (int j = 0; j < 2; ++j) {
        fx[0][j] = xp[j * RF4];
        fm[0][j] = mp[j * RF4];
    }

    #pragma unroll
    for (int c = 0; c < 18; ++c) {
        const int cur = c & 1, nxt = cur ^ 1;
        if (c < 17) {
            #pragma unroll
            for (int j = 0; j < 2; ++j) {
                fx[nxt][j] = xp[(2 * (c + 1) + j) * RF4];
                fm[nxt][j] = mp[(2 * (c + 1) + j) * RF4];
            }
        } else {
            fx[nxt][0] = xp[36 * RF4];   // epilogue sensor 36
            fm[nxt][0] = mp[36 * RF4];
        }
        #pragma unroll
        for (int j = 0; j < 2; ++j) {
            const int s = 2 * c + j;
            const float4 xv = fx[cur][j];
            const int4   mv = fm[cur][j];

            float ax = (xv.x + xv.y) + (xv.z + xv.w);
            float am = (float)((mv.x + mv.y) + (mv.z + mv.w));

            nz0 += fabsf(xv.x) + (float)mv.x;
            nz1 += fabsf(xv.y) + (float)mv.y;
            nz2 += fabsf(xv.z) + (float)mv.z;
            nz3 += fabsf(xv.w) + (float)mv.w;

            ax = wred3(ax);
            am = wred3(am);
            if (lane < 4) {
                myrow[s * 4 + lane]        = ax;
                myrow[(SS + s) * 4 + lane] = am;
            }
        }
    }
    {   // epilogue: sensor 36 (after c=17, nxt buffer = 0^1... c=17 cur=1 nxt=0)
        const float4 xv = fx[0][0];
        const int4   mv = fm[0][0];
        float ax = (xv.x + xv.y) + (xv.z + xv.w);
        float am = (float)((mv.x + mv.y) + (mv.z + mv.w));
        nz0 += fabsf(xv.x) + (float)mv.x;
        nz1 += fabsf(xv.y) + (float)mv.y;
        nz2 += fabsf(xv.z) + (float)mv.z;
        nz3 += fabsf(xv.w) + (float)mv.w;
        ax = wred3(ax);
        am = wred3(am);
        if (lane < 4) {
            myrow[36 * 4 + lane]        = ax;
            myrow[(SS + 36) * 4 + lane] = am;
        }
    }

    // mask count + masked time sum
    {
        float ms = 0.f, tm = 0.f;
        if (nz0 > 0.f) { ms += 1.f; tm += tv.x; }
        if (nz1 > 0.f) { ms += 1.f; tm += tv.y; }
        if (nz2 > 0.f) { ms += 1.f; tm += tv.z; }
        if (nz3 > 0.f) { ms += 1.f; tm += tv.w; }
        ms = wred3(ms);
        tm = wred3(tm);
        if (lane < 4) {
            myrow[74 * 4 + lane] = ms;
            myrow[75 * 4 + lane] = tm;
        }
    }
    __syncthreads();

    // final combine: 76 outputs, 16 warp-rows x 4 partials each
    if (tid < 76) {
        float acc = 0.f;
        #pragma unroll
        for (int w2 = 0; w2 < 16; ++w2) {
            const float4 p = *(const float4*)&sW[w2 * PW + tid * 4];
            acc += (p.x + p.y) + (p.z + p.w);
        }
        sAll[tid] = acc;
    }
    __syncthreads();

    // ================= Phase 2: per-batch tail (L2-warm) =================
    const float msum  = sAll[74];
    const float tmsum = sAll[75];
    const float inv   = 1.f / fmaxf(msum, 1e-9f);

    // ---- A: comb[MER] ----
    if (tid < DD) {
        float acc = 0.f;
        #pragma unroll 8
        for (int f = 0; f < NF; ++f) acc += sAll[f] * Ws[f * DD + tid];
        acc += msum * (bs[tid] + bt[tid]) + tmsum * Wt[tid];
        comb[tid] = acc * inv;
    } else if (tid < MER) {
        const int j = tid - DD;
        float acc = bst[j];
        #pragma unroll
        for (int q = 0; q < STT; ++q) acc += stat[b * STT + q] * Wst[q * STT + j];
        comb[tid] = acc;
    }
    __syncthreads();

    // ---- B: merge GEMV split-i, float4 columns ----
    if (tid < G2 * Q2) {
        const int q  = tid % Q2;
        const int gg = tid / Q2;
        const float4* __restrict__ Wm4 = (const float4*)Wm;
        float4 acc = make_float4(0.f, 0.f, 0.f, 0.f);
        #pragma unroll
        for (int kk = 0; kk < KI2; ++kk) {
            const int ii = gg * KI2 + kk;
            const float  c  = comb[ii];
            const float4 wv = Wm4[ii * Q2 + q];
            acc.x += c * wv.x;
            acc.y += c * wv.y;
            acc.z += c * wv.z;
            acc.w += c * wv.w;
        }
        sH4[gg * Q2 + q] = acc;
    }
    __syncthreads();

    // ---- C: reduce, ReLU, classifier ----
    float p0 = 0.f, p1 = 0.f;
    if (tid < MER) {
        const float* sH = (const float*)sH4;
        float t = bm[tid];
        #pragma unroll
        for (int gg = 0; gg < G2; ++gg) t += sH[gg * MER + tid];
        const float h = fmaxf(t, 0.f);
        p0 = h * Wc[tid * CC + 0];
        p1 = h * Wc[tid * CC + 1];
    }
    p0 = wredf(p0);
    p1 = wredf(p1);
    if (lane == 0) {
        atomicAdd(&outc[0], p0);
        atomicAdd(&outc[1], p1);
    }
    __syncthreads();

    if (tid < CC) out[b * CC + tid] = outc[tid] + bc[tid];
}

// ---------------- launch ----------------
extern "C" void kernel_launch(void* const* d_in, const int* in_sizes, int n_in,
                              void* d_out, int out_size) {
    const float* x     = (const float*)d_in[0];
    const float* stat  = (const float*)d_in[1];
    const float* tim   = (const float*)d_in[2];
    const int*   smask = (const int*)  d_in[3];
    const float* Ws    = (const float*)d_in[4];
    const float* bs    = (const float*)d_in[5];
    const float* Wt    = (const float*)d_in[6];
    const float* bt    = (const float*)d_in[7];
    const float* Wst   = (const float*)d_in[8];
    const float* bst   = (const float*)d_in[9];
    const float* Wm    = (const float*)d_in[10];
    const float* bm    = (const float*)d_in[11];
    const float* Wc    = (const float*)d_in[12];
    const float* bc    = (const float*)d_in[13];
    float* out = (float*)d_out;

    fused_kernel<<<BB, NT>>>(x, smask, tim, stat, Ws, bs, Wt, bt,
                             Wst, bst, Wm, bm, Wc, bc, out);
}